// round 6
// baseline (speedup 1.0000x reference)
#include <cuda_runtime.h>
#include <math.h>
#include <stdint.h>

// ---------------------------------------------------------------------------
// Problem constants
// ---------------------------------------------------------------------------
#define B_   2
#define S_   2048
#define DM   2048      // d_model
#define NH_  16        // n_heads
#define HD   128       // head_dim
#define NHD  2048      // NH_*HD
#define M_   (B_*S_)   // 4096 rows in prefill GEMMs

// ---------------------------------------------------------------------------
// Scratch (device globals: no allocations allowed)
// ---------------------------------------------------------------------------
__device__ float g_Q[(size_t)B_*S_*NHD];
__device__ float g_K[(size_t)B_*S_*NHD];
__device__ float g_V[(size_t)B_*S_*NHD];
__device__ float g_O[(size_t)B_*S_*NHD];
__device__ float g_q1[B_*NHD];
__device__ float g_k1[B_*NHD];
__device__ float g_v1[B_*NHD];
__device__ float g_o1[B_*NHD];

// ---------------------------------------------------------------------------
// SGEMM: C[M,N] = A[M,K] * B       (BT=0: B is [K,N] row-major)
//        C[M,N] = A[M,K] * B^T     (BT=1: B is [N,K] row-major)
// 128x128x8 tiles, 8x8 per thread, double-buffered smem, float4 I/O.
// M,N,K assumed multiples of 128 / 8 (true here).
// ---------------------------------------------------------------------------
template<int BT>
__global__ __launch_bounds__(256, 2)
void sgemm_kernel(const float* __restrict__ A, const float* __restrict__ Bm,
                  float* __restrict__ C, int M, int N, int K)
{
    __shared__ float As[2][8][132];
    __shared__ float Bs[2][8][132];

    const int tid = threadIdx.x;
    const int bm  = blockIdx.y << 7;
    const int bn  = blockIdx.x << 7;
    const int tx  = tid & 15, ty = tid >> 4;
    const int lr  = tid >> 1;               // 0..127 (A / BT loader row)
    const int lc  = (tid & 1) << 2;         // 0 or 4 (k offset)
    const int bnr = tid >> 5;               // 0..7  (NN loader k row)
    const int bnc = (tid & 31) << 2;        // 0..124 (NN loader col)

    float4 av, bv;

    // prefetch tile 0
    av = *(const float4*)(A + (size_t)(bm + lr) * K + lc);
    if (BT) bv = *(const float4*)(Bm + (size_t)(bn + lr) * K + lc);
    else    bv = *(const float4*)(Bm + (size_t)bnr * N + bn + bnc);

    As[0][lc+0][lr] = av.x; As[0][lc+1][lr] = av.y;
    As[0][lc+2][lr] = av.z; As[0][lc+3][lr] = av.w;
    if (BT) {
        Bs[0][lc+0][lr] = bv.x; Bs[0][lc+1][lr] = bv.y;
        Bs[0][lc+2][lr] = bv.z; Bs[0][lc+3][lr] = bv.w;
    } else {
        *(float4*)&Bs[0][bnr][bnc] = bv;
    }
    __syncthreads();

    float acc[8][8];
#pragma unroll
    for (int i = 0; i < 8; ++i)
#pragma unroll
        for (int j = 0; j < 8; ++j) acc[i][j] = 0.f;

    const int nk = K >> 3;
    for (int t = 0; t < nk; ++t) {
        const int cur = t & 1;
        if (t + 1 < nk) {
            const int kb = (t + 1) << 3;
            av = *(const float4*)(A + (size_t)(bm + lr) * K + kb + lc);
            if (BT) bv = *(const float4*)(Bm + (size_t)(bn + lr) * K + kb + lc);
            else    bv = *(const float4*)(Bm + (size_t)(kb + bnr) * N + bn + bnc);
        }
#pragma unroll
        for (int kk = 0; kk < 8; ++kk) {
            float a[8], b[8];
            *(float4*)&a[0] = *(const float4*)&As[cur][kk][(ty << 3)];
            *(float4*)&a[4] = *(const float4*)&As[cur][kk][(ty << 3) + 4];
            *(float4*)&b[0] = *(const float4*)&Bs[cur][kk][(tx << 3)];
            *(float4*)&b[4] = *(const float4*)&Bs[cur][kk][(tx << 3) + 4];
#pragma unroll
            for (int i = 0; i < 8; ++i)
#pragma unroll
                for (int j = 0; j < 8; ++j)
                    acc[i][j] = fmaf(a[i], b[j], acc[i][j]);
        }
        if (t + 1 < nk) {
            const int nxt = cur ^ 1;
            As[nxt][lc+0][lr] = av.x; As[nxt][lc+1][lr] = av.y;
            As[nxt][lc+2][lr] = av.z; As[nxt][lc+3][lr] = av.w;
            if (BT) {
                Bs[nxt][lc+0][lr] = bv.x; Bs[nxt][lc+1][lr] = bv.y;
                Bs[nxt][lc+2][lr] = bv.z; Bs[nxt][lc+3][lr] = bv.w;
            } else {
                *(float4*)&Bs[nxt][bnr][bnc] = bv;
            }
            __syncthreads();
        }
    }

#pragma unroll
    for (int i = 0; i < 8; ++i) {
        float* cp = C + (size_t)(bm + (ty << 3) + i) * N + bn + (tx << 3);
        float4 v0 = make_float4(acc[i][0], acc[i][1], acc[i][2], acc[i][3]);
        float4 v1 = make_float4(acc[i][4], acc[i][5], acc[i][6], acc[i][7]);
        *(float4*)cp       = v0;
        *(float4*)(cp + 4) = v1;
    }
}

// ---------------------------------------------------------------------------
// Flash attention, causal prefill.
// One block per (q_tile of 64 rows, head n, batch b). 256 threads.
// Q,K stored transposed in smem for conflict-free S=QK^T; V natural for PV.
// ---------------------------------------------------------------------------
#define QST_STRIDE 68
#define FP_SMEM_FLOATS (128*QST_STRIDE + 128*QST_STRIDE + 64*128 + 64*QST_STRIDE)

__global__ __launch_bounds__(256)
void flash_prefill_kernel()
{
    extern __shared__ float sm[];
    float* Qst = sm;                                   // [128][68] (k-major)
    float* Kst = sm + 128*QST_STRIDE;                  // [128][68]
    float* Vs  = sm + 2*128*QST_STRIDE;                // [64][128]
    float* Ss  = sm + 2*128*QST_STRIDE + 64*128;       // [64][68]

    const int tid = threadIdx.x;
    const int qt  = blockIdx.x;
    const int n   = blockIdx.y;
    const int b   = blockIdx.z;
    const int q0  = qt << 6;
    const size_t base = ((size_t)b * S_ * NH_ + n) * HD;  // (b, s=0, n, 0)

    // ---- load Q tile transposed: Qst[h][r] = Q[q0+r][h] ----
#pragma unroll
    for (int it = 0; it < 8; ++it) {
        int i  = tid + (it << 8);        // float4 index, 0..2047
        int r  = i & 63;
        int c4 = (i >> 6) << 2;
        float4 v = *(const float4*)(g_Q + base + (size_t)(q0 + r) * NHD + c4);
        Qst[(c4+0)*QST_STRIDE + r] = v.x;
        Qst[(c4+1)*QST_STRIDE + r] = v.y;
        Qst[(c4+2)*QST_STRIDE + r] = v.z;
        Qst[(c4+3)*QST_STRIDE + r] = v.w;
    }

    float o[32];
#pragma unroll
    for (int c = 0; c < 32; ++c) o[c] = 0.f;
    float mrow = -INFINITY, lrow = 0.f;

    const int r   = tid >> 2;     // softmax/PV: row 0..63
    const int cq  = tid & 3;      // column quarter
    const int sty = tid >> 4;     // S stage: rows sty*4..+3
    const int stx = tid & 15;     // S stage: cols stx*4..+3
    const float scale = 0.088388347648318447f;  // 1/sqrt(128)

    __syncthreads();

    for (int kt = 0; kt <= qt; ++kt) {
        const int k0 = kt << 6;
        // K transposed
#pragma unroll
        for (int it = 0; it < 8; ++it) {
            int i  = tid + (it << 8);
            int rr = i & 63;
            int c4 = (i >> 6) << 2;
            float4 v = *(const float4*)(g_K + base + (size_t)(k0 + rr) * NHD + c4);
            Kst[(c4+0)*QST_STRIDE + rr] = v.x;
            Kst[(c4+1)*QST_STRIDE + rr] = v.y;
            Kst[(c4+2)*QST_STRIDE + rr] = v.z;
            Kst[(c4+3)*QST_STRIDE + rr] = v.w;
        }
        // V natural (coalesced)
#pragma unroll
        for (int it = 0; it < 8; ++it) {
            int i  = tid + (it << 8);
            int rr = i >> 5;
            int c4 = (i & 31) << 2;
            *(float4*)(Vs + rr*128 + c4) =
                *(const float4*)(g_V + base + (size_t)(k0 + rr) * NHD + c4);
        }
        __syncthreads();

        // ---- S = Q K^T, 4x4 micro per thread ----
        float sa[4][4];
#pragma unroll
        for (int i = 0; i < 4; ++i)
#pragma unroll
            for (int j = 0; j < 4; ++j) sa[i][j] = 0.f;

#pragma unroll 4
        for (int k = 0; k < 128; ++k) {
            float4 aq = *(const float4*)(Qst + k*QST_STRIDE + (sty << 2));
            float4 bk = *(const float4*)(Kst + k*QST_STRIDE + (stx << 2));
            sa[0][0] = fmaf(aq.x, bk.x, sa[0][0]);
            sa[0][1] = fmaf(aq.x, bk.y, sa[0][1]);
            sa[0][2] = fmaf(aq.x, bk.z, sa[0][2]);
            sa[0][3] = fmaf(aq.x, bk.w, sa[0][3]);
            sa[1][0] = fmaf(aq.y, bk.x, sa[1][0]);
            sa[1][1] = fmaf(aq.y, bk.y, sa[1][1]);
            sa[1][2] = fmaf(aq.y, bk.z, sa[1][2]);
            sa[1][3] = fmaf(aq.y, bk.w, sa[1][3]);
            sa[2][0] = fmaf(aq.z, bk.x, sa[2][0]);
            sa[2][1] = fmaf(aq.z, bk.y, sa[2][1]);
            sa[2][2] = fmaf(aq.z, bk.z, sa[2][2]);
            sa[2][3] = fmaf(aq.z, bk.w, sa[2][3]);
            sa[3][0] = fmaf(aq.w, bk.x, sa[3][0]);
            sa[3][1] = fmaf(aq.w, bk.y, sa[3][1]);
            sa[3][2] = fmaf(aq.w, bk.z, sa[3][2]);
            sa[3][3] = fmaf(aq.w, bk.w, sa[3][3]);
        }
#pragma unroll
        for (int i = 0; i < 4; ++i) {
            int rr = (sty << 2) + i;
#pragma unroll
            for (int j = 0; j < 4; ++j) {
                int jj = (stx << 2) + j;
                float s = sa[i][j] * scale;
                if (kt == qt && jj > rr) s = -INFINITY;  // causal on diagonal tile
                Ss[rr*QST_STRIDE + jj] = s;
            }
        }
        __syncthreads();

        // ---- online softmax: thread (r,cq) owns j in [cq*16, cq*16+16) ----
        float sv[16];
        float mloc = -INFINITY;
#pragma unroll
        for (int j = 0; j < 16; ++j) {
            sv[j] = Ss[r*QST_STRIDE + (cq << 4) + j];
            mloc  = fmaxf(mloc, sv[j]);
        }
        mloc = fmaxf(mloc, __shfl_xor_sync(0xffffffffu, mloc, 1));
        mloc = fmaxf(mloc, __shfl_xor_sync(0xffffffffu, mloc, 2));
        float mnew = fmaxf(mrow, mloc);
        float corr = __expf(mrow - mnew);

        float lloc = 0.f;
#pragma unroll
        for (int j = 0; j < 16; ++j) {
            float p = __expf(sv[j] - mnew);
            Ss[r*QST_STRIDE + (cq << 4) + j] = p;
            lloc += p;
        }
        lloc += __shfl_xor_sync(0xffffffffu, lloc, 1);
        lloc += __shfl_xor_sync(0xffffffffu, lloc, 2);
        lrow = lrow * corr + lloc;
        mrow = mnew;
#pragma unroll
        for (int c = 0; c < 32; ++c) o[c] *= corr;
        __syncwarp();   // P row written by this row's 4 lanes (same warp)

        // ---- O += P V : thread (r,cq) accumulates cols [cq*32, cq*32+32) ----
        const float* vbase = Vs + (cq << 5);
        const float* prow  = Ss + r*QST_STRIDE;
#pragma unroll 4
        for (int j = 0; j < 64; ++j) {
            float p = prow[j];
            const float* vr = vbase + j*128;
#pragma unroll
            for (int c4 = 0; c4 < 8; ++c4) {
                float4 v = *(const float4*)(vr + (c4 << 2));
                o[(c4<<2)+0] = fmaf(p, v.x, o[(c4<<2)+0]);
                o[(c4<<2)+1] = fmaf(p, v.y, o[(c4<<2)+1]);
                o[(c4<<2)+2] = fmaf(p, v.z, o[(c4<<2)+2]);
                o[(c4<<2)+3] = fmaf(p, v.w, o[(c4<<2)+3]);
            }
        }
        __syncthreads();  // before next tile overwrites Kst/Vs/Ss
    }

    const float inv = 1.f / lrow;
    float* op = g_O + base + (size_t)(q0 + r) * NHD + (cq << 5);
#pragma unroll
    for (int c4 = 0; c4 < 8; ++c4) {
        float4 v = make_float4(o[(c4<<2)+0]*inv, o[(c4<<2)+1]*inv,
                               o[(c4<<2)+2]*inv, o[(c4<<2)+3]*inv);
        *(float4*)(op + (c4 << 2)) = v;
    }
}

// ---------------------------------------------------------------------------
// Decode: x_new[b] @ W  ->  out[b][2048]   (coalesced column GEMV)
// grid (16, B), 128 threads.
// ---------------------------------------------------------------------------
__global__ __launch_bounds__(128)
void decode_proj_kernel(const float* __restrict__ xn, const float* __restrict__ W,
                        float* __restrict__ out)
{
    __shared__ float xs[DM];
    const int b = blockIdx.y;
    for (int i = threadIdx.x; i < DM; i += 128)
        xs[i] = xn[b*DM + i];
    __syncthreads();

    const int col = (blockIdx.x << 7) + threadIdx.x;
    float a0 = 0.f, a1 = 0.f, a2 = 0.f, a3 = 0.f;
    for (int k = 0; k < DM; k += 4) {
        a0 = fmaf(xs[k+0], W[(size_t)(k+0)*NHD + col], a0);
        a1 = fmaf(xs[k+1], W[(size_t)(k+1)*NHD + col], a1);
        a2 = fmaf(xs[k+2], W[(size_t)(k+2)*NHD + col], a2);
        a3 = fmaf(xs[k+3], W[(size_t)(k+3)*NHD + col], a3);
    }
    out[b*NHD + col] = (a0 + a1) + (a2 + a3);
}

// ---------------------------------------------------------------------------
// Decode attention: one block per (b,n), attends q1 over 2049 cached keys.
// ---------------------------------------------------------------------------
__global__ __launch_bounds__(256)
void decode_attn_kernel()
{
    __shared__ float q[HD];
    __shared__ float sc[S_ + 32];
    __shared__ float red[8];
    __shared__ float obuf[HD];

    const int bn  = blockIdx.x;
    const int b   = bn >> 4, n = bn & 15;
    const int tid = threadIdx.x;
    const int wid = tid >> 5, lane = tid & 31;
    const float scale = 0.088388347648318447f;

    if (tid < HD) q[tid] = g_q1[b*NHD + n*HD + tid];
    __syncthreads();

    // scores: warp-per-key (coalesced 512B per warp per key)
    for (int j = wid; j < S_ + 1; j += 8) {
        const float* kr = (j < S_)
            ? (g_K + ((size_t)(b*S_ + j) * NH_ + n) * HD)
            : (g_k1 + b*NHD + n*HD);
        float4 k4 = *(const float4*)(kr + (lane << 2));
        float s = q[(lane<<2)+0]*k4.x + q[(lane<<2)+1]*k4.y
                + q[(lane<<2)+2]*k4.z + q[(lane<<2)+3]*k4.w;
#pragma unroll
        for (int off = 16; off > 0; off >>= 1)
            s += __shfl_xor_sync(0xffffffffu, s, off);
        if (lane == 0) sc[j] = s * scale;
    }
    __syncthreads();

    // block max
    float lm = -INFINITY;
    for (int j = tid; j < S_ + 1; j += 256) lm = fmaxf(lm, sc[j]);
#pragma unroll
    for (int off = 16; off > 0; off >>= 1)
        lm = fmaxf(lm, __shfl_xor_sync(0xffffffffu, lm, off));
    if (lane == 0) red[wid] = lm;
    __syncthreads();
    float Mx = -INFINITY;
#pragma unroll
    for (int w = 0; w < 8; ++w) Mx = fmaxf(Mx, red[w]);
    __syncthreads();   // red reused below

    // exp + block sum
    float ls = 0.f;
    for (int j = tid; j < S_ + 1; j += 256) {
        float e = __expf(sc[j] - Mx);
        sc[j] = e;
        ls += e;
    }
#pragma unroll
    for (int off = 16; off > 0; off >>= 1)
        ls += __shfl_xor_sync(0xffffffffu, ls, off);
    if (lane == 0) red[wid] = ls;
    __syncthreads();
    float L = 0.f;
#pragma unroll
    for (int w = 0; w < 8; ++w) L += red[w];

    // O = P @ V : thread owns output col h for half the keys
    const int h = tid & 127, half = tid >> 7;
    const float* vb = g_V + ((size_t)b*S_*NH_ + n) * HD + h;
    float a0 = 0.f, a1 = 0.f, a2 = 0.f, a3 = 0.f;
    for (int j = half; j < S_; j += 8) {
        a0 = fmaf(sc[j+0], vb[(size_t)(j+0)*NHD], a0);
        a1 = fmaf(sc[j+2], vb[(size_t)(j+2)*NHD], a1);
        a2 = fmaf(sc[j+4], vb[(size_t)(j+4)*NHD], a2);
        a3 = fmaf(sc[j+6], vb[(size_t)(j+6)*NHD], a3);
    }
    float acc = (a0 + a1) + (a2 + a3);
    if (half == 1) {
        acc = fmaf(sc[S_], g_v1[b*NHD + n*HD + h], acc);
        obuf[h] = acc;
    }
    __syncthreads();
    if (half == 0)
        g_o1[b*NHD + n*HD + h] = (acc + obuf[h]) / L;
}

// ---------------------------------------------------------------------------
// Decode output projection: out[b][d] = sum_nh o1[b][nh] * wo[d][nh]
// grid (256, B), 256 threads: one warp per d.
// ---------------------------------------------------------------------------
__global__ __launch_bounds__(256)
void decode_oproj_kernel(const float* __restrict__ wo, float* __restrict__ out)
{
    __shared__ float os[NHD];
    const int b = blockIdx.y;
    for (int i = threadIdx.x; i < NHD; i += 256)
        os[i] = g_o1[b*NHD + i];
    __syncthreads();

    const int wid = threadIdx.x >> 5, lane = threadIdx.x & 31;
    const int d = (blockIdx.x << 3) + wid;
    float acc = 0.f;
    for (int k4 = lane; k4 < NHD/4; k4 += 32) {
        float4 w  = *(const float4*)(wo + (size_t)d*NHD + (k4 << 2));
        float4 o4 = *(const float4*)(os + (k4 << 2));
        acc += w.x*o4.x + w.y*o4.y + w.z*o4.z + w.w*o4.w;
    }
#pragma unroll
    for (int off = 16; off > 0; off >>= 1)
        acc += __shfl_xor_sync(0xffffffffu, acc, off);
    if (lane == 0) out[b*DM + d] = acc;
}

// ---------------------------------------------------------------------------
// Launch
// ---------------------------------------------------------------------------
extern "C" void kernel_launch(void* const* d_in, const int* in_sizes, int n_in,
                              void* d_out, int out_size)
{
    const float* x     = (const float*)d_in[0];
    const float* x_new = (const float*)d_in[1];
    const float* wq    = (const float*)d_in[2];
    const float* wk    = (const float*)d_in[3];
    const float* wv    = (const float*)d_in[4];
    const float* wo    = (const float*)d_in[5];
    float* out = (float*)d_out;

    float *Q, *K, *V, *O, *q1, *k1, *v1;
    cudaGetSymbolAddress((void**)&Q,  g_Q);
    cudaGetSymbolAddress((void**)&K,  g_K);
    cudaGetSymbolAddress((void**)&V,  g_V);
    cudaGetSymbolAddress((void**)&O,  g_O);
    cudaGetSymbolAddress((void**)&q1, g_q1);
    cudaGetSymbolAddress((void**)&k1, g_k1);
    cudaGetSymbolAddress((void**)&v1, g_v1);

    const dim3 blk(256);
    const dim3 g_proj(NHD / 128, M_ / 128);   // (16, 32)

    // QKV projections
    sgemm_kernel<0><<<g_proj, blk>>>(x, wq, Q, M_, NHD, DM);
    sgemm_kernel<0><<<g_proj, blk>>>(x, wk, K, M_, NHD, DM);
    sgemm_kernel<0><<<g_proj, blk>>>(x, wv, V, M_, NHD, DM);

    // Flash attention (causal prefill)
    const int fa_smem = FP_SMEM_FLOATS * (int)sizeof(float);
    cudaFuncSetAttribute(flash_prefill_kernel,
                         cudaFuncAttributeMaxDynamicSharedMemorySize, fa_smem);
    flash_prefill_kernel<<<dim3(S_/64, NH_, B_), blk, fa_smem>>>();

    // Prefill output projection: out = O @ Wo^T  (Wo is [d][nh])
    sgemm_kernel<1><<<dim3(DM / 128, M_ / 128), blk>>>(O, wo, out, M_, DM, NHD);

    // Decode path
    decode_proj_kernel<<<dim3(NHD/128, B_), 128>>>(x_new, wq, q1);
    decode_proj_kernel<<<dim3(NHD/128, B_), 128>>>(x_new, wk, k1);
    decode_proj_kernel<<<dim3(NHD/128, B_), 128>>>(x_new, wv, v1);
    decode_attn_kernel<<<B_ * NH_, 256>>>();
    decode_oproj_kernel<<<dim3(DM/8, B_), 256>>>(wo, out + (size_t)M_ * DM);
}

// round 11
// speedup vs baseline: 4.7098x; 4.7098x over previous
#include <cuda_runtime.h>
#include <cuda_bf16.h>
#include <math.h>
#include <stdint.h>

// ---------------------------------------------------------------------------
// Problem constants
// ---------------------------------------------------------------------------
#define B_   2
#define S_   2048
#define DM   2048      // d_model
#define NH_  16        // n_heads
#define HD   128       // head_dim
#define NHD  2048      // NH_*HD
#define M_   (B_*S_)   // 4096 rows in prefill GEMMs
#define ZB   (B_*NH_)  // 32 attention batches

typedef __nv_bfloat16  bf16;
typedef __nv_bfloat162 bf162;

// ---------------------------------------------------------------------------
// Scratch (device globals: no allocations allowed)
// ---------------------------------------------------------------------------
__device__ bf16 g_xh[(size_t)M_*DM],  g_xl[(size_t)M_*DM];
__device__ bf16 g_wqh[(size_t)DM*NHD], g_wql[(size_t)DM*NHD];
__device__ bf16 g_wkh[(size_t)DM*NHD], g_wkl[(size_t)DM*NHD];
__device__ bf16 g_wvh[(size_t)DM*NHD], g_wvl[(size_t)DM*NHD];
__device__ bf16 g_woh[(size_t)DM*NHD], g_wol[(size_t)DM*NHD];
// Q/K/V head-major: [b][n][s][h]
__device__ bf16 g_Qh[(size_t)ZB*S_*HD], g_Ql[(size_t)ZB*S_*HD];
__device__ bf16 g_Kh[(size_t)ZB*S_*HD], g_Kl[(size_t)ZB*S_*HD];
__device__ bf16 g_Vh[(size_t)ZB*S_*HD], g_Vl[(size_t)ZB*S_*HD];
// logits, then (in-place) softmax probabilities: [z][s][t]
__device__ bf16 g_Ph[(size_t)ZB*S_*S_], g_Pl[(size_t)ZB*S_*S_];
// attention output, seq-major: [b*S+s][n*HD+h]
__device__ bf16 g_Oh[(size_t)M_*NHD],  g_Ol[(size_t)M_*NHD];
// decode scratch (fp32)
__device__ float g_q1[B_*NHD];
__device__ float g_k1[B_*NHD];
__device__ float g_v1[B_*NHD];
__device__ float g_o1[B_*NHD];

// ---------------------------------------------------------------------------
// PTX helpers
// ---------------------------------------------------------------------------
__device__ __forceinline__ void cp16(uint32_t s, const void* g) {
    asm volatile("cp.async.cg.shared.global [%0], [%1], 16;" :: "r"(s), "l"(g));
}
__device__ __forceinline__ void cp_commit() {
    asm volatile("cp.async.commit_group;");
}
template<int N>
__device__ __forceinline__ void cp_wait() {
    asm volatile("cp.async.wait_group %0;" :: "n"(N));
}
__device__ __forceinline__ void ldsm4(uint32_t (&r)[4], uint32_t addr) {
    asm volatile("ldmatrix.sync.aligned.m8n8.x4.shared.b16 {%0,%1,%2,%3}, [%4];"
                 : "=r"(r[0]), "=r"(r[1]), "=r"(r[2]), "=r"(r[3]) : "r"(addr));
}
__device__ __forceinline__ void ldsm4t(uint32_t (&r)[4], uint32_t addr) {
    asm volatile("ldmatrix.sync.aligned.m8n8.x4.trans.shared.b16 {%0,%1,%2,%3}, [%4];"
                 : "=r"(r[0]), "=r"(r[1]), "=r"(r[2]), "=r"(r[3]) : "r"(addr));
}
__device__ __forceinline__ void mma16816(float (&c)[4], const uint32_t (&a)[4],
                                         uint32_t b0, uint32_t b1) {
    asm volatile(
        "mma.sync.aligned.m16n8k16.row.col.f32.bf16.bf16.f32 "
        "{%0,%1,%2,%3},{%4,%5,%6,%7},{%8,%9},{%0,%1,%2,%3};"
        : "+f"(c[0]), "+f"(c[1]), "+f"(c[2]), "+f"(c[3])
        : "r"(a[0]), "r"(a[1]), "r"(a[2]), "r"(a[3]), "r"(b0), "r"(b1));
}

// ---------------------------------------------------------------------------
// Unified split-bf16 tensor-core GEMM.
//   C = (Ah+Al) * (Bh+Bl)  dropping the Al*Bl term.
// BT=0: C[M,N] = A[M,K] * B[K,N]      (B row-major [K][N])
// BT=1: C[M,N] = A[M,K] * B[N,K]^T    (B row-major [N][K])
// SPLIT=1: write Ch/Cl (bf16 hi/lo); SPLIT=0: write C (fp32)
// OUTMAP: 0 = row*ldc+col (+z*sC); 1 = QKV head-major remap; 2 = PV seq-major remap
// CAUSAL=1: skip blocks entirely above the diagonal (for S = QK^T)
// KLIM=1:   k range clipped at bm0+128 (for O = PV with causal-zero P)
// Tiles: BM=BN=128, BK=32, 256 threads (8 warps as 4x2), warp tile 32x64.
// ---------------------------------------------------------------------------
template<int BT, int SPLIT, int OUTMAP, int CAUSAL, int KLIM>
__global__ __launch_bounds__(256)
void hgemm(const bf16* __restrict__ Ah, const bf16* __restrict__ Al,
           const bf16* __restrict__ Bh, const bf16* __restrict__ Bl,
           float* __restrict__ C, bf16* __restrict__ Ch, bf16* __restrict__ Cl,
           int K, int lda, int ldb, int ldc,
           size_t sA, size_t sB, size_t sC)
{
    constexpr int ABYTES = 128 * 40 * 2;                  // padded [128][40] bf16
    constexpr int BBYTES = BT ? 128 * 40 * 2 : 32 * 136 * 2;
    constexpr int STAGE  = 2 * ABYTES + 2 * BBYTES;

    const int tid  = threadIdx.x;
    const int lane = tid & 31, warp = tid >> 5;
    const int bm0  = blockIdx.y << 7, bn0 = blockIdx.x << 7;
    if (CAUSAL && bn0 > bm0) return;
    const int z = blockIdx.z;

    Ah += (size_t)z * sA;  Al += (size_t)z * sA;
    Bh += (size_t)z * sB;  Bl += (size_t)z * sB;

    const int kend = KLIM ? min(K, bm0 + 128) : K;
    const int nt   = kend >> 5;

    extern __shared__ __align__(16) unsigned char smem_raw[];
    const uint32_t smem_u32 = (uint32_t)__cvta_generic_to_shared(smem_raw);

    const int wm0 = (warp >> 1) << 5;   // 0,32,64,96
    const int wn0 = (warp & 1) << 6;    // 0,64

    auto issue = [&](int t, int stg) {
        const uint32_t sb = smem_u32 + stg * STAGE;
        const int k0 = t << 5;
#pragma unroll
        for (int cc = 0; cc < 2; ++cc) {
            const int idx = tid + (cc << 8);
            {   // A tiles (h and l): 128 rows x 32 bf16
                const int r = idx >> 2, c = (idx & 3) << 3;
                const size_t go = (size_t)(bm0 + r) * lda + k0 + c;
                const uint32_t so = (uint32_t)(r * 80 + c * 2);
                cp16(sb + so,          Ah + go);
                cp16(sb + ABYTES + so, Al + go);
            }
            if (BT) {   // B as [N][K]: same shape as A
                const int r = idx >> 2, c = (idx & 3) << 3;
                const size_t go = (size_t)(bn0 + r) * ldb + k0 + c;
                const uint32_t so = (uint32_t)(r * 80 + c * 2);
                cp16(sb + 2*ABYTES + so,          Bh + go);
                cp16(sb + 2*ABYTES + BBYTES + so, Bl + go);
            } else {    // B as [K][N]: 32 rows x 128 bf16
                const int r = idx >> 4, c = (idx & 15) << 3;
                const size_t go = (size_t)(k0 + r) * ldb + bn0 + c;
                const uint32_t so = (uint32_t)(r * 272 + c * 2);
                cp16(sb + 2*ABYTES + so,          Bh + go);
                cp16(sb + 2*ABYTES + BBYTES + so, Bl + go);
            }
        }
    };

    float acc[2][8][4];
#pragma unroll
    for (int i = 0; i < 2; ++i)
#pragma unroll
        for (int j = 0; j < 8; ++j)
#pragma unroll
            for (int k = 0; k < 4; ++k) acc[i][j][k] = 0.f;

    issue(0, 0);
    cp_commit();

    for (int t = 0; t < nt; ++t) {
        if (t + 1 < nt) { issue(t + 1, (t + 1) & 1); cp_commit(); cp_wait<1>(); }
        else            { cp_wait<0>(); }
        __syncthreads();

        const uint32_t sb = smem_u32 + (t & 1) * STAGE;
#pragma unroll
        for (int ks = 0; ks < 32; ks += 16) {
            uint32_t ah[2][4], al[2][4], bh[8][2], bl[8][2];
            // A fragments (row-major, non-trans x4)
#pragma unroll
            for (int mt = 0; mt < 2; ++mt) {
                const int row = wm0 + mt * 16 + (lane & 15);
                const uint32_t ad = sb + row * 80 + (ks + ((lane >> 4) << 3)) * 2;
                ldsm4(ah[mt], ad);
                ldsm4(al[mt], ad + ABYTES);
            }
            // B fragments
            const int g = lane >> 3, tr = lane & 7;
            const int selk = (g & 1) << 3, seln = (g >> 1) << 3;
#pragma unroll
            for (int q4 = 0; q4 < 4; ++q4) {
                const int n0 = wn0 + q4 * 16;
                uint32_t bd;
                if (BT) bd = sb + 2*ABYTES + (uint32_t)(n0 + seln + tr) * 80 + (ks + selk) * 2;
                else    bd = sb + 2*ABYTES + (uint32_t)(ks + selk + tr) * 272 + (n0 + seln) * 2;
                uint32_t R[4];
                if (BT) ldsm4(R, bd); else ldsm4t(R, bd);
                bh[2*q4][0] = R[0]; bh[2*q4][1] = R[1];
                bh[2*q4+1][0] = R[2]; bh[2*q4+1][1] = R[3];
                if (BT) ldsm4(R, bd + BBYTES); else ldsm4t(R, bd + BBYTES);
                bl[2*q4][0] = R[0]; bl[2*q4][1] = R[1];
                bl[2*q4+1][0] = R[2]; bl[2*q4+1][1] = R[3];
            }
            // 3-term split MMA
#pragma unroll
            for (int mt = 0; mt < 2; ++mt)
#pragma unroll
                for (int nn = 0; nn < 8; ++nn) {
                    mma16816(acc[mt][nn], ah[mt], bh[nn][0], bh[nn][1]);
                    mma16816(acc[mt][nn], ah[mt], bl[nn][0], bl[nn][1]);
                    mma16816(acc[mt][nn], al[mt], bh[nn][0], bh[nn][1]);
                }
        }
        __syncthreads();
    }

    // ---- epilogue ----
    auto store2 = [&](int row, int col, float x, float y) {
        if (SPLIT == 0) {
            float2 v = make_float2(x, y);
            *(float2*)(C + (size_t)z * sC + (size_t)row * ldc + col) = v;
        } else {
            size_t idx;
            if (OUTMAP == 0) {
                idx = (size_t)z * sC + (size_t)row * ldc + col;
            } else if (OUTMAP == 1) {   // QKV head-major: [b][n][s][h]
                const int b = row >> 11, s = row & 2047;
                const int n = col >> 7,  h = col & 127;
                idx = (((size_t)(b * NH_ + n)) * S_ + s) * HD + h;
            } else {                    // PV seq-major: [b*S+s][n*HD+h]
                const int b = z >> 4, n = z & 15;
                idx = ((size_t)(b * S_) + row) * NHD + n * HD + col;
            }
            const bf16 hx = __float2bfloat16(x), hy = __float2bfloat16(y);
            bf162 hv; hv.x = hx; hv.y = hy;
            bf162 lv;
            lv.x = __float2bfloat16(x - __bfloat162float(hx));
            lv.y = __float2bfloat16(y - __bfloat162float(hy));
            *(bf162*)(Ch + idx) = hv;
            *(bf162*)(Cl + idx) = lv;
        }
    };

#pragma unroll
    for (int mt = 0; mt < 2; ++mt)
#pragma unroll
        for (int nn = 0; nn < 8; ++nn) {
            const int rr = bm0 + wm0 + mt * 16 + (lane >> 2);
            const int cc = bn0 + wn0 + nn * 8 + ((lane & 3) << 1);
            store2(rr,     cc, acc[mt][nn][0], acc[mt][nn][1]);
            store2(rr + 8, cc, acc[mt][nn][2], acc[mt][nn][3]);
        }
}

// ---------------------------------------------------------------------------
// fp32 -> (bf16 hi, bf16 lo) split
// ---------------------------------------------------------------------------
__global__ __launch_bounds__(256)
void split_kernel(const float* __restrict__ in, bf16* __restrict__ h,
                  bf16* __restrict__ l, int n4)
{
    const int i = blockIdx.x * 256 + threadIdx.x;
    if (i >= n4) return;
    const float4 v = ((const float4*)in)[i];
    const bf16 h0 = __float2bfloat16(v.x), h1 = __float2bfloat16(v.y);
    const bf16 h2 = __float2bfloat16(v.z), h3 = __float2bfloat16(v.w);
    bf162 a; a.x = h0; a.y = h1;
    bf162 b; b.x = h2; b.y = h3;
    ((bf162*)h)[2*i]   = a;
    ((bf162*)h)[2*i+1] = b;
    bf162 c, d;
    c.x = __float2bfloat16(v.x - __bfloat162float(h0));
    c.y = __float2bfloat16(v.y - __bfloat162float(h1));
    d.x = __float2bfloat16(v.z - __bfloat162float(h2));
    d.y = __float2bfloat16(v.w - __bfloat162float(h3));
    ((bf162*)l)[2*i]   = c;
    ((bf162*)l)[2*i+1] = d;
}

// ---------------------------------------------------------------------------
// Causal softmax over logits (split-bf16, in place): one warp per row.
// Reads g_Ph/g_Pl (logits), writes normalized probabilities back, zero-fills
// the tail of the row's own 128-block (needed by the KLIM PV GEMM).
// ---------------------------------------------------------------------------
__global__ __launch_bounds__(256)
void softmax_kernel()
{
    const int z    = blockIdx.y;
    const int s    = blockIdx.x * 8 + (threadIdx.x >> 5);
    const int lane = threadIdx.x & 31;
    const float scale = 0.088388347648318447f;  // 1/sqrt(128)

    bf16* ph = g_Ph + (size_t)z * S_ * S_ + (size_t)s * S_;
    bf16* pl = g_Pl + (size_t)z * S_ * S_ + (size_t)s * S_;
    const int cnt = s + 1;

    float m = -INFINITY;
    for (int j = lane; j < cnt; j += 32) {
        const float v = __bfloat162float(ph[j]) + __bfloat162float(pl[j]);
        m = fmaxf(m, v);
    }
#pragma unroll
    for (int off = 16; off > 0; off >>= 1)
        m = fmaxf(m, __shfl_xor_sync(0xffffffffu, m, off));

    float sum = 0.f;
    for (int j = lane; j < cnt; j += 32) {
        const float v = __bfloat162float(ph[j]) + __bfloat162float(pl[j]);
        sum += __expf((v - m) * scale);
    }
#pragma unroll
    for (int off = 16; off > 0; off >>= 1)
        sum += __shfl_xor_sync(0xffffffffu, sum, off);
    const float inv = 1.f / sum;

    for (int j = lane; j < cnt; j += 32) {
        const float v = __bfloat162float(ph[j]) + __bfloat162float(pl[j]);
        const float p = __expf((v - m) * scale) * inv;
        const bf16 hp = __float2bfloat16(p);
        ph[j] = hp;
        pl[j] = __float2bfloat16(p - __bfloat162float(hp));
    }
    const int fend = ((s >> 7) + 1) << 7;
    const bf16 zero = __float2bfloat16(0.f);
    for (int j = cnt + lane; j < fend; j += 32) { ph[j] = zero; pl[j] = zero; }
}

// ---------------------------------------------------------------------------
// Decode: x_new[b] @ W -> out[b][2048]   (fp32, coalesced column GEMV)
// ---------------------------------------------------------------------------
__global__ __launch_bounds__(128)
void decode_proj_kernel(const float* __restrict__ xn, const float* __restrict__ W,
                        float* __restrict__ out)
{
    __shared__ float xs[DM];
    const int b = blockIdx.y;
    for (int i = threadIdx.x; i < DM; i += 128)
        xs[i] = xn[b*DM + i];
    __syncthreads();

    const int col = (blockIdx.x << 7) + threadIdx.x;
    float a0 = 0.f, a1 = 0.f, a2 = 0.f, a3 = 0.f;
    for (int k = 0; k < DM; k += 4) {
        a0 = fmaf(xs[k+0], W[(size_t)(k+0)*NHD + col], a0);
        a1 = fmaf(xs[k+1], W[(size_t)(k+1)*NHD + col], a1);
        a2 = fmaf(xs[k+2], W[(size_t)(k+2)*NHD + col], a2);
        a3 = fmaf(xs[k+3], W[(size_t)(k+3)*NHD + col], a3);
    }
    out[b*NHD + col] = (a0 + a1) + (a2 + a3);
}

// ---------------------------------------------------------------------------
// Decode attention: one block per (b,n); K/V cache read from head-major
// split-bf16 buffers (value = hi + lo).
// ---------------------------------------------------------------------------
__global__ __launch_bounds__(256)
void decode_attn_kernel()
{
    __shared__ float q[HD];
    __shared__ float sc[S_ + 32];
    __shared__ float red[8];
    __shared__ float obuf[HD];

    const int bn  = blockIdx.x;
    const int b   = bn >> 4, n = bn & 15;
    const int tid = threadIdx.x;
    const int wid = tid >> 5, lane = tid & 31;
    const float scale = 0.088388347648318447f;
    const size_t hb = (size_t)(b * NH_ + n) * S_ * HD;   // head-major base

    if (tid < HD) q[tid] = g_q1[b*NHD + n*HD + tid];
    __syncthreads();

    // scores: warp-per-key
    for (int j = wid; j < S_ + 1; j += 8) {
        float s;
        if (j < S_) {
            const bf16* krh = g_Kh + hb + (size_t)j * HD;
            const bf16* krl = g_Kl + hb + (size_t)j * HD;
            s = 0.f;
#pragma unroll
            for (int ii = 0; ii < 4; ++ii) {
                const int idx = (lane << 2) + ii;
                const float kv = __bfloat162float(krh[idx]) + __bfloat162float(krl[idx]);
                s = fmaf(q[idx], kv, s);
            }
        } else {
            const float* kr = g_k1 + b*NHD + n*HD;
            s = 0.f;
#pragma unroll
            for (int ii = 0; ii < 4; ++ii) {
                const int idx = (lane << 2) + ii;
                s = fmaf(q[idx], kr[idx], s);
            }
        }
#pragma unroll
        for (int off = 16; off > 0; off >>= 1)
            s += __shfl_xor_sync(0xffffffffu, s, off);
        if (lane == 0) sc[j] = s * scale;
    }
    __syncthreads();

    // block max
    float lm = -INFINITY;
    for (int j = tid; j < S_ + 1; j += 256) lm = fmaxf(lm, sc[j]);
#pragma unroll
    for (int off = 16; off > 0; off >>= 1)
        lm = fmaxf(lm, __shfl_xor_sync(0xffffffffu, lm, off));
    if (lane == 0) red[wid] = lm;
    __syncthreads();
    float Mx = -INFINITY;
#pragma unroll
    for (int w = 0; w < 8; ++w) Mx = fmaxf(Mx, red[w]);
    __syncthreads();

    // exp + block sum
    float ls = 0.f;
    for (int j = tid; j < S_ + 1; j += 256) {
        const float e = __expf(sc[j] - Mx);
        sc[j] = e;
        ls += e;
    }
#pragma unroll
    for (int off = 16; off > 0; off >>= 1)
        ls += __shfl_xor_sync(0xffffffffu, ls, off);
    if (lane == 0) red[wid] = ls;
    __syncthreads();
    float L = 0.f;
#pragma unroll
    for (int w = 0; w < 8; ++w) L += red[w];

    // O = P @ V
    const int h = tid & 127, half = tid >> 7;
    const bf16* vbh = g_Vh + hb + h;
    const bf16* vbl = g_Vl + hb + h;
    float acc = 0.f;
    for (int j = half; j < S_; j += 2) {
        const float vv = __bfloat162float(vbh[(size_t)j * HD])
                       + __bfloat162float(vbl[(size_t)j * HD]);
        acc = fmaf(sc[j], vv, acc);
    }
    if (half == 1) {
        acc = fmaf(sc[S_], g_v1[b*NHD + n*HD + h], acc);
        obuf[h] = acc;
    }
    __syncthreads();
    if (half == 0)
        g_o1[b*NHD + n*HD + h] = (acc + obuf[h]) / L;
}

// ---------------------------------------------------------------------------
// Decode output projection: out[b][d] = sum_nh o1[b][nh] * wo[d][nh]
// ---------------------------------------------------------------------------
__global__ __launch_bounds__(256)
void decode_oproj_kernel(const float* __restrict__ wo, float* __restrict__ out)
{
    __shared__ float os[NHD];
    const int b = blockIdx.y;
    for (int i = threadIdx.x; i < NHD; i += 256)
        os[i] = g_o1[b*NHD + i];
    __syncthreads();

    const int wid = threadIdx.x >> 5, lane = threadIdx.x & 31;
    const int d = (blockIdx.x << 3) + wid;
    float acc = 0.f;
    for (int k4 = lane; k4 < NHD/4; k4 += 32) {
        const float4 w  = *(const float4*)(wo + (size_t)d*NHD + (k4 << 2));
        const float4 o4 = *(const float4*)(os + (k4 << 2));
        acc += w.x*o4.x + w.y*o4.y + w.z*o4.z + w.w*o4.w;
    }
#pragma unroll
    for (int off = 16; off > 0; off >>= 1)
        acc += __shfl_xor_sync(0xffffffffu, acc, off);
    if (lane == 0) out[b*DM + d] = acc;
}

// ---------------------------------------------------------------------------
// Launch
// ---------------------------------------------------------------------------
extern "C" void kernel_launch(void* const* d_in, const int* in_sizes, int n_in,
                              void* d_out, int out_size)
{
    const float* x     = (const float*)d_in[0];
    const float* x_new = (const float*)d_in[1];
    const float* wq    = (const float*)d_in[2];
    const float* wk    = (const float*)d_in[3];
    const float* wv    = (const float*)d_in[4];
    const float* wo    = (const float*)d_in[5];
    float* out = (float*)d_out;

    bf16 *xh, *xl, *wqh, *wql, *wkh, *wkl, *wvh, *wvl, *woh, *wol;
    bf16 *Qh, *Ql, *Kh, *Kl, *Vh, *Vl, *Ph, *Pl, *Oh, *Ol;
    float *q1, *k1, *v1;
    cudaGetSymbolAddress((void**)&xh,  g_xh);  cudaGetSymbolAddress((void**)&xl,  g_xl);
    cudaGetSymbolAddress((void**)&wqh, g_wqh); cudaGetSymbolAddress((void**)&wql, g_wql);
    cudaGetSymbolAddress((void**)&wkh, g_wkh); cudaGetSymbolAddress((void**)&wkl, g_wkl);
    cudaGetSymbolAddress((void**)&wvh, g_wvh); cudaGetSymbolAddress((void**)&wvl, g_wvl);
    cudaGetSymbolAddress((void**)&woh, g_woh); cudaGetSymbolAddress((void**)&wol, g_wol);
    cudaGetSymbolAddress((void**)&Qh,  g_Qh);  cudaGetSymbolAddress((void**)&Ql,  g_Ql);
    cudaGetSymbolAddress((void**)&Kh,  g_Kh);  cudaGetSymbolAddress((void**)&Kl,  g_Kl);
    cudaGetSymbolAddress((void**)&Vh,  g_Vh);  cudaGetSymbolAddress((void**)&Vl,  g_Vl);
    cudaGetSymbolAddress((void**)&Ph,  g_Ph);  cudaGetSymbolAddress((void**)&Pl,  g_Pl);
    cudaGetSymbolAddress((void**)&Oh,  g_Oh);  cudaGetSymbolAddress((void**)&Ol,  g_Ol);
    cudaGetSymbolAddress((void**)&q1,  g_q1);
    cudaGetSymbolAddress((void**)&k1,  g_k1);
    cudaGetSymbolAddress((void**)&v1,  g_v1);

    // opt-in dynamic smem (>48KB) for each instantiation
    const int smemNT = 2 * (2*128*40*2 + 2*128*40*2);   // 81920 B
    const int smemNN = 2 * (2*128*40*2 + 2*32*136*2);   // 75776 B
    cudaFuncSetAttribute(hgemm<0,1,1,0,0>, cudaFuncAttributeMaxDynamicSharedMemorySize, smemNN);
    cudaFuncSetAttribute(hgemm<1,1,0,1,0>, cudaFuncAttributeMaxDynamicSharedMemorySize, smemNT);
    cudaFuncSetAttribute(hgemm<0,1,2,0,1>, cudaFuncAttributeMaxDynamicSharedMemorySize, smemNN);
    cudaFuncSetAttribute(hgemm<1,0,0,0,0>, cudaFuncAttributeMaxDynamicSharedMemorySize, smemNT);

    // ---- split fp32 inputs into bf16 hi/lo ----
    {
        const int n4x = (M_*DM)/4, n4w = (DM*NHD)/4;
        split_kernel<<<(n4x+255)/256, 256>>>(x,  xh,  xl,  n4x);
        split_kernel<<<(n4w+255)/256, 256>>>(wq, wqh, wql, n4w);
        split_kernel<<<(n4w+255)/256, 256>>>(wk, wkh, wkl, n4w);
        split_kernel<<<(n4w+255)/256, 256>>>(wv, wvh, wvl, n4w);
        split_kernel<<<(n4w+255)/256, 256>>>(wo, woh, wol, n4w);
    }

    // ---- QKV projections: [4096x2048x2048] NN, split-out head-major ----
    {
        const dim3 g(NHD/128, M_/128, 1), blk(256);
        hgemm<0,1,1,0,0><<<g, blk, smemNN>>>(xh, xl, wqh, wql, nullptr, Qh, Ql,
                                             DM, DM, NHD, 0, 0, 0, 0);
        hgemm<0,1,1,0,0><<<g, blk, smemNN>>>(xh, xl, wkh, wkl, nullptr, Kh, Kl,
                                             DM, DM, NHD, 0, 0, 0, 0);
        hgemm<0,1,1,0,0><<<g, blk, smemNN>>>(xh, xl, wvh, wvl, nullptr, Vh, Vl,
                                             DM, DM, NHD, 0, 0, 0, 0);
    }

    // ---- S = Q K^T: batched 32 x [2048x2048x128] NT, causal block skip ----
    {
        const dim3 g(S_/128, S_/128, ZB), blk(256);
        hgemm<1,1,0,1,0><<<g, blk, smemNT>>>(Qh, Ql, Kh, Kl, nullptr, Ph, Pl,
                                             HD, HD, HD, S_,
                                             (size_t)S_*HD, (size_t)S_*HD, (size_t)S_*S_);
    }

    // ---- softmax (in place, causal) ----
    softmax_kernel<<<dim3(S_/8, ZB), 256>>>();

    // ---- O = P V: batched 32 x [2048x128x2048] NN, k clipped at diagonal ----
    {
        const dim3 g(1, S_/128, ZB), blk(256);
        hgemm<0,1,2,0,1><<<g, blk, smemNN>>>(Ph, Pl, Vh, Vl, nullptr, Oh, Ol,
                                             S_, S_, HD, 0,
                                             (size_t)S_*S_, (size_t)S_*HD, 0);
    }

    // ---- prefill output projection: out = O @ Wo^T (fp32) ----
    {
        const dim3 g(DM/128, M_/128, 1), blk(256);
        hgemm<1,0,0,0,0><<<g, blk, smemNT>>>(Oh, Ol, woh, wol, out, nullptr, nullptr,
                                             NHD, NHD, NHD, DM, 0, 0, 0);
    }

    // ---- decode path ----
    decode_proj_kernel<<<dim3(NHD/128, B_), 128>>>(x_new, wq, q1);
    decode_proj_kernel<<<dim3(NHD/128, B_), 128>>>(x_new, wk, k1);
    decode_proj_kernel<<<dim3(NHD/128, B_), 128>>>(x_new, wv, v1);
    decode_attn_kernel<<<B_ * NH_, 256>>>();
    decode_oproj_kernel<<<dim3(DM/8, B_), 256>>>(wo, out + (size_t)M_ * DM);
}